// round 3
// baseline (speedup 1.0000x reference)
#include <cuda_runtime.h>

#define BS 2
#define NB 6300
#define NA 85
#define NC 80
#define TOT (BS * NB)

#define CONF_T  0.5f
#define NMS_T   0.4f
#define SCORE_T 0.3f

// -------- device scratch (static allocation; no runtime allocs) --------
__device__ float4        g_box[TOT];          // x1,y1,x2,y2 (masked)
__device__ float         g_pobj[TOT];
__device__ float         g_maxsc[TOT];
__device__ int           g_cls[TOT];
__device__ unsigned char g_keep[TOT];
__device__ int           g_cnt[BS * NC];
__device__ int           g_lst[BS * NC * NB]; // unsorted per-class lists (global box idx)
__device__ int           g_srt[BS * NC * NB]; // sorted per-class lists

// -------- kernel 0: zero per-class counters --------
__global__ void zero_cnt_kernel() {
    int t = blockIdx.x * blockDim.x + threadIdx.x;
    if (t < BS * NC) g_cnt[t] = 0;
}

// -------- kernel 1: per-box preprocess (one warp per box) --------
__global__ void prep_kernel(const float* __restrict__ x) {
    int wid  = (blockIdx.x * blockDim.x + threadIdx.x) >> 5; // global box index
    int lane = threadIdx.x & 31;
    if (wid >= TOT) return;

    const float* p = x + (size_t)wid * NA;
    // coalesced strided read of the 85 attributes
    float v0 = p[lane];                                   // j = lane (0..31)
    float v1 = p[lane + 32];                              // j = 32..63
    float v2 = (lane + 64 < NA) ? p[lane + 64] : -3.4e38f; // j = 64..84

    // first-max over class scores j in [5, 85)
    float bv = -3.4e38f; int bj = 0x7fffffff;
    if (lane >= 5) { bv = v0; bj = lane; }
    {
        int j1 = lane + 32;
        if (v1 > bv || (v1 == bv && j1 < bj)) { bv = v1; bj = j1; }
        int j2 = lane + 64;
        if (j2 < NA && (v2 > bv || (v2 == bv && j2 < bj))) { bv = v2; bj = j2; }
    }
    #pragma unroll
    for (int off = 16; off; off >>= 1) {
        float ov = __shfl_xor_sync(0xffffffffu, bv, off);
        int   oj = __shfl_xor_sync(0xffffffffu, bj, off);
        if (ov > bv || (ov == bv && oj < bj)) { bv = ov; bj = oj; }
    }

    // broadcast box attrs from lanes 0..4
    float cx = __shfl_sync(0xffffffffu, v0, 0);
    float cy = __shfl_sync(0xffffffffu, v0, 1);
    float w  = __shfl_sync(0xffffffffu, v0, 2);
    float h  = __shfl_sync(0xffffffffu, v0, 3);
    float ob = __shfl_sync(0xffffffffu, v0, 4);

    if (lane == 0) {
        bool conf = ob > CONF_T;
        float x1, y1, x2, y2, pobj, ms; int cls;
        if (conf) {
            x1 = cx - w * 0.5f; y1 = cy - h * 0.5f;
            x2 = cx + w * 0.5f; y2 = cy + h * 0.5f;
            pobj = ob; ms = bv; cls = bj - 5;
        } else {
            x1 = y1 = x2 = y2 = 0.f; pobj = 0.f; ms = 0.f; cls = 0;
        }
        g_box[wid]   = make_float4(x1, y1, x2, y2);
        g_pobj[wid]  = pobj;
        g_maxsc[wid] = ms;
        g_cls[wid]   = cls;
        g_keep[wid]  = 0;
        if (conf && ms > SCORE_T) {
            int b    = wid / NB;
            int cidx = b * NC + cls;
            int pos  = atomicAdd(&g_cnt[cidx], 1);
            g_lst[cidx * NB + pos] = wid;
        }
    }
}

// -------- kernel 2: per-(image,class) greedy NMS (one warp per block) --------
__global__ void nms_kernel() {
    int c = blockIdx.x;            // 0 .. BS*NC-1
    int k = g_cnt[c];
    if (k == 0) return;
    int lane = threadIdx.x;
    const int base = c * NB;

    // O(k^2) rank sort: key = (pobj desc, global_idx asc)  -> deterministic
    for (int p = lane; p < k; p += 32) {
        int   ip = g_lst[base + p];
        float sp = g_pobj[ip];
        int r = 0;
        for (int q = 0; q < k; q++) {
            int   iq = g_lst[base + q];
            float sq = g_pobj[iq];
            r += (sq > sp) || (sq == sp && iq < ip);
        }
        g_srt[base + r] = ip;
    }
    __syncwarp();

    __shared__ unsigned char kept[NB];
    for (int p = lane; p < k; p += 32) kept[p] = 1;
    __syncwarp();

    for (int r = 0; r < k; r++) {
        if (!kept[r]) continue;                  // uniform across the warp
        int    ir    = g_srt[base + r];
        float4 br    = g_box[ir];
        float  areaR = (br.z - br.x) * (br.w - br.y);
        for (int p = r + 1 + lane; p < k; p += 32) {
            if (!kept[p]) continue;
            int    ip = g_srt[base + p];
            float4 bp = g_box[ip];
            float iw = fminf(br.z, bp.z) - fmaxf(br.x, bp.x); iw = fmaxf(iw, 0.f);
            float ih = fminf(br.w, bp.w) - fmaxf(br.y, bp.y); ih = fmaxf(ih, 0.f);
            float inter = iw * ih;
            float areaP = (bp.z - bp.x) * (bp.w - bp.y);
            float iou   = inter / (areaR + areaP - inter + 1e-16f);
            if (iou >= NMS_T) kept[p] = 0;
        }
        __syncwarp();
    }

    for (int p = lane; p < k; p += 32)
        g_keep[g_srt[base + p]] = kept[p];
}

// -------- kernel 3: write [BS, NB, 8] output (zeros for suppressed) --------
__global__ void out_kernel(float* __restrict__ out) {
    int gi = blockIdx.x * blockDim.x + threadIdx.x;
    if (gi >= TOT) return;
    float4 o0 = make_float4(0.f, 0.f, 0.f, 0.f);
    float4 o1 = o0;
    if (g_keep[gi]) {
        float4 b = g_box[gi];
        o0 = make_float4((float)(gi / NB), b.x, b.y, b.z);
        o1 = make_float4(b.w, g_pobj[gi], g_maxsc[gi], (float)g_cls[gi]);
    }
    float4* po = (float4*)(out + (size_t)gi * 8);
    po[0] = o0;
    po[1] = o1;
}

extern "C" void kernel_launch(void* const* d_in, const int* in_sizes, int n_in,
                              void* d_out, int out_size) {
    const float* x   = (const float*)d_in[0];
    float*       out = (float*)d_out;

    zero_cnt_kernel<<<1, BS * NC>>>();

    // one warp per box: TOT warps, 8 warps/block
    int prep_blocks = (TOT * 32 + 255) / 256;
    prep_kernel<<<prep_blocks, 256>>>(x);

    nms_kernel<<<BS * NC, 32>>>();

    out_kernel<<<(TOT + 255) / 256, 256>>>(out);
}

// round 4
// speedup vs baseline: 1.1709x; 1.1709x over previous
#include <cuda_runtime.h>

#define BS 2
#define NB 6300
#define NA 85
#define NC 80
#define TOT (BS * NB)

#define CONF_T  0.5f
#define NMS_T   0.4f
#define SCORE_T 0.3f

#define SMAX 1024   // shared-memory fast path capacity per (image,class)

// -------- device scratch (static allocation; no runtime allocs) --------
__device__ float4        g_box[TOT];          // x1,y1,x2,y2 (masked)
__device__ float         g_pobj[TOT];
__device__ float         g_maxsc[TOT];
__device__ int           g_cls[TOT];
__device__ unsigned char g_keep[TOT];         // zero-initialized; out_kernel re-zeros after use
__device__ int           g_cnt[BS * NC];      // zero-initialized; nms_kernel re-zeros after use
__device__ int           g_lst[BS * NC * NB]; // unsorted per-class lists (global box idx)
__device__ int           g_srt[BS * NC * NB]; // sorted lists (fallback path only)

// -------- kernel 1: per-box preprocess (one warp per box) --------
__global__ void prep_kernel(const float* __restrict__ x) {
    int wid  = (blockIdx.x * blockDim.x + threadIdx.x) >> 5; // global box index
    int lane = threadIdx.x & 31;
    if (wid >= TOT) return;

    const float* p = x + (size_t)wid * NA;
    float v0 = p[lane];                                    // j = 0..31
    float v1 = p[lane + 32];                               // j = 32..63
    float v2 = (lane + 64 < NA) ? p[lane + 64] : -3.4e38f; // j = 64..84

    // first-max over class scores j in [5, 85)
    float bv = -3.4e38f; int bj = 0x7fffffff;
    if (lane >= 5) { bv = v0; bj = lane; }
    {
        int j1 = lane + 32;
        if (v1 > bv || (v1 == bv && j1 < bj)) { bv = v1; bj = j1; }
        int j2 = lane + 64;
        if (j2 < NA && (v2 > bv || (v2 == bv && j2 < bj))) { bv = v2; bj = j2; }
    }
    #pragma unroll
    for (int off = 16; off; off >>= 1) {
        float ov = __shfl_xor_sync(0xffffffffu, bv, off);
        int   oj = __shfl_xor_sync(0xffffffffu, bj, off);
        if (ov > bv || (ov == bv && oj < bj)) { bv = ov; bj = oj; }
    }

    float cx = __shfl_sync(0xffffffffu, v0, 0);
    float cy = __shfl_sync(0xffffffffu, v0, 1);
    float w  = __shfl_sync(0xffffffffu, v0, 2);
    float h  = __shfl_sync(0xffffffffu, v0, 3);
    float ob = __shfl_sync(0xffffffffu, v0, 4);

    if (lane == 0) {
        bool conf = ob > CONF_T;
        float x1, y1, x2, y2, pobj, ms; int cls;
        if (conf) {
            x1 = cx - w * 0.5f; y1 = cy - h * 0.5f;
            x2 = cx + w * 0.5f; y2 = cy + h * 0.5f;
            pobj = ob; ms = bv; cls = bj - 5;
        } else {
            x1 = y1 = x2 = y2 = 0.f; pobj = 0.f; ms = 0.f; cls = 0;
        }
        g_box[wid]   = make_float4(x1, y1, x2, y2);
        g_pobj[wid]  = pobj;
        g_maxsc[wid] = ms;
        g_cls[wid]   = cls;
        if (conf && ms > SCORE_T) {
            int b    = wid / NB;
            int cidx = b * NC + cls;
            int pos  = atomicAdd(&g_cnt[cidx], 1);
            g_lst[cidx * NB + pos] = wid;
        }
    }
}

// -------- kernel 2: per-(image,class) greedy NMS (one warp per block) --------
__global__ void nms_kernel() {
    int c = blockIdx.x;            // 0 .. BS*NC-1
    int lane = threadIdx.x;
    int k = g_cnt[c];
    if (lane == 0) g_cnt[c] = 0;   // self-reset for next graph replay
    if (k == 0) return;
    const int base = c * NB;

    if (k <= SMAX) {
        // ---------- shared-memory fast path ----------
        __shared__ float         s_sc[SMAX];
        __shared__ int           s_idx[SMAX];
        __shared__ int           s_srt[SMAX];
        __shared__ float4        s_box[SMAX];
        __shared__ unsigned char s_kept[SMAX];

        // stage (score, global idx)
        for (int p = lane; p < k; p += 32) {
            int i = g_lst[base + p];
            s_idx[p] = i;
            s_sc[p]  = g_pobj[i];
        }
        __syncwarp();

        // O(k^2) rank sort on smem: key = (pobj desc, global_idx asc)
        for (int p = lane; p < k; p += 32) {
            float sp = s_sc[p];
            int   ip = s_idx[p];
            int r = 0;
            for (int q = 0; q < k; q++) {
                float sq = s_sc[q];
                int   iq = s_idx[q];
                r += (sq > sp) || (sq == sp && iq < ip);
            }
            s_srt[r] = ip;
        }
        __syncwarp();

        // gather boxes in sorted order
        for (int p = lane; p < k; p += 32) {
            s_box[p]  = g_box[s_srt[p]];
            s_kept[p] = 1;
        }
        __syncwarp();

        // greedy suppression, all in smem
        for (int r = 0; r < k; r++) {
            if (!s_kept[r]) continue;           // warp-uniform
            float4 br    = s_box[r];
            float  areaR = (br.z - br.x) * (br.w - br.y);
            for (int p = r + 1 + lane; p < k; p += 32) {
                if (!s_kept[p]) continue;
                float4 bp = s_box[p];
                float iw = fminf(br.z, bp.z) - fmaxf(br.x, bp.x); iw = fmaxf(iw, 0.f);
                float ih = fminf(br.w, bp.w) - fmaxf(br.y, bp.y); ih = fmaxf(ih, 0.f);
                float inter = iw * ih;
                float areaP = (bp.z - bp.x) * (bp.w - bp.y);
                float iou   = inter / (areaR + areaP - inter + 1e-16f);
                if (iou >= NMS_T) s_kept[p] = 0;
            }
            __syncwarp();
        }

        for (int p = lane; p < k; p += 32)
            if (s_kept[p]) g_keep[s_srt[p]] = 1;
    } else {
        // ---------- global fallback (k > SMAX; essentially never taken) ----------
        for (int p = lane; p < k; p += 32) {
            int   ip = g_lst[base + p];
            float sp = g_pobj[ip];
            int r = 0;
            for (int q = 0; q < k; q++) {
                int   iq = g_lst[base + q];
                float sq = g_pobj[iq];
                r += (sq > sp) || (sq == sp && iq < ip);
            }
            g_srt[base + r] = ip;
        }
        __syncwarp();

        __shared__ unsigned char keptg[NB];
        for (int p = lane; p < k; p += 32) keptg[p] = 1;
        __syncwarp();

        for (int r = 0; r < k; r++) {
            if (!keptg[r]) continue;
            int    ir    = g_srt[base + r];
            float4 br    = g_box[ir];
            float  areaR = (br.z - br.x) * (br.w - br.y);
            for (int p = r + 1 + lane; p < k; p += 32) {
                if (!keptg[p]) continue;
                int    ip = g_srt[base + p];
                float4 bp = g_box[ip];
                float iw = fminf(br.z, bp.z) - fmaxf(br.x, bp.x); iw = fmaxf(iw, 0.f);
                float ih = fminf(br.w, bp.w) - fmaxf(br.y, bp.y); ih = fmaxf(ih, 0.f);
                float inter = iw * ih;
                float areaP = (bp.z - bp.x) * (bp.w - bp.y);
                float iou   = inter / (areaR + areaP - inter + 1e-16f);
                if (iou >= NMS_T) keptg[p] = 0;
            }
            __syncwarp();
        }

        for (int p = lane; p < k; p += 32)
            if (keptg[p]) g_keep[g_srt[base + p]] = 1;
    }
}

// -------- kernel 3: write [BS, NB, 8] output, branchless, self-reset keep --------
__global__ void out_kernel(float* __restrict__ out) {
    int gi = blockIdx.x * blockDim.x + threadIdx.x;
    if (gi >= TOT) return;

    // issue all loads up front (MLP), then predicate by multiply
    unsigned char kp = g_keep[gi];
    float4 b    = g_box[gi];
    float  pobj = g_pobj[gi];
    float  ms   = g_maxsc[gi];
    int    cls  = g_cls[gi];

    g_keep[gi] = 0;                 // self-reset for next graph replay

    float f = kp ? 1.0f : 0.0f;
    float bidx = (float)(gi / NB);

    float4 o0 = make_float4(f * bidx, f * b.x, f * b.y, f * b.z);
    float4 o1 = make_float4(f * b.w, f * pobj, f * ms, f * (float)cls);

    float4* po = (float4*)(out + (size_t)gi * 8);
    po[0] = o0;
    po[1] = o1;
}

extern "C" void kernel_launch(void* const* d_in, const int* in_sizes, int n_in,
                              void* d_out, int out_size) {
    const float* x   = (const float*)d_in[0];
    float*       out = (float*)d_out;

    // one warp per box
    int prep_blocks = (TOT * 32 + 255) / 256;
    prep_kernel<<<prep_blocks, 256>>>(x);

    nms_kernel<<<BS * NC, 32>>>();

    out_kernel<<<(TOT + 255) / 256, 256>>>(out);
}